// round 14
// baseline (speedup 1.0000x reference)
#include <cuda_runtime.h>
#include <cuda_bf16.h>

// ContrastiveLoss via closed-form separable reduction, ONE fused kernel.
// loss = [(N-1)(Sx+Sy) - 2*dot(colsum_x, colsum_y) + 2*sum_i x_i.y_i] / (2N(N-1))
// Label is unused.
//
// 148 blocks x 1024 threads — one CTA on EVERY SM (prior rounds left 20 SMs
// idle); per-SM ingest drops 13.5%. Each thread: 1-2 float4 loads per tensor
// (front-batched LDG.128). Two-level last-block election with uneven group
// sizes (148 = 4 groups of 10 + 12 groups of 9). Fixed-order reductions ->
// deterministic across graph replays; last block resets counters.

#define NBLK 148
#define NTHR 1024
#define NTOT (NBLK * NTHR)      // 151552 threads (== 0 mod 32: col groups ok)
#define DCOLS 128
#define NGRP 16                 // election groups; sizes 10 (k<4) or 9

__device__ float4 g_csx4[NBLK * 32];   // per-block column sums (128 cols)
__device__ float4 g_csy4[NBLK * 32];
__device__ float  g_ssx[NBLK];
__device__ float  g_ssy[NBLK];
__device__ float  g_dxy[NBLK];

struct __align__(128) PadCtr { unsigned int v; unsigned int pad[31]; };
__device__ PadCtr g_grp[NGRP];         // zero-init; last block resets
__device__ PadCtr g_super;

__device__ __forceinline__ float dot4(float4 a, float4 b) {
    return fmaf(a.x, b.x, fmaf(a.y, b.y, fmaf(a.z, b.z, a.w * b.w)));
}
__device__ __forceinline__ float4 f4add(float4 a, float4 b) {
    return make_float4(a.x + b.x, a.y + b.y, a.z + b.z, a.w + b.w);
}

__global__ void __launch_bounds__(NTHR, 1)
cl_fused_kernel(const float4* __restrict__ f1,
                const float4* __restrict__ f2,
                int total4,          // N * 32 float4 per tensor (262144)
                int N,
                float* __restrict__ out)
{
    const int t = threadIdx.x;
    const int b = blockIdx.x;
    const int g = b * NTHR + t;
    const int s = t >> 5;            // warp id 0..31
    const int lane = t & 31;

    // ---- Phase 1: 1-2 float4 per tensor, all loads front-batched ----
    float4 z = make_float4(0.f, 0.f, 0.f, 0.f);
    float4 x0 = z, x1 = z, y0 = z, y1 = z;
    if (g        < total4) { x0 = f1[g];        y0 = f2[g];        }
    if (g + NTOT < total4) { x1 = f1[g + NTOT]; y1 = f2[g + NTOT]; }

    float4 cx4 = f4add(x0, x1);
    float4 cy4 = f4add(y0, y1);
    float ssx = dot4(x0, x0) + dot4(x1, x1);
    float ssy = dot4(y0, y0) + dot4(y1, y1);
    float dxy = dot4(x0, y0) + dot4(x1, y1);

    // ---- Block reduce colsums: sum float4 across the 32 warps per lane ----
    __shared__ float4 shx[NTHR];     // 16 KB, reused by finalize
    __shared__ float4 shy[NTHR];     // 16 KB
    shx[t] = cx4;
    shy[t] = cy4;
    __syncthreads();
    if (t < 32) {
        float4 ax = shx[t], ay = shy[t];
        #pragma unroll
        for (int w = 1; w < 32; w++) {
            ax = f4add(ax, shx[w * 32 + t]);
            ay = f4add(ay, shy[w * 32 + t]);
        }
        g_csx4[b * 32 + t] = ax;     // coalesced 512B store
        g_csy4[b * 32 + t] = ay;
    }

    // ---- Block reduce the 3 scalars (shuffle tree, fixed order) ----
    {
        float a = ssx, e = ssy, d = dxy;
        #pragma unroll
        for (int o = 16; o; o >>= 1) {
            a += __shfl_down_sync(0xffffffffu, a, o);
            e += __shfl_down_sync(0xffffffffu, e, o);
            d += __shfl_down_sync(0xffffffffu, d, o);
        }
        __shared__ float w0[32], w1[32], w2[32];
        if (lane == 0) { w0[s] = a; w1[s] = e; w2[s] = d; }
        __syncthreads();
        if (s == 0) {
            float a2 = w0[lane], e2 = w1[lane], d2 = w2[lane];
            #pragma unroll
            for (int o = 16; o; o >>= 1) {
                a2 += __shfl_down_sync(0xffffffffu, a2, o);
                e2 += __shfl_down_sync(0xffffffffu, e2, o);
                d2 += __shfl_down_sync(0xffffffffu, d2, o);
            }
            if (lane == 0) { g_ssx[b] = a2; g_ssy[b] = e2; g_dxy[b] = d2; }
        }
    }

    // ---- Two-level last-block election (uneven groups, short chains) ----
    // Group k = b & 15 holds blocks {b : b mod 16 == k}: 10 blocks for k<4,
    // 9 for k>=4 (148 = 16*9 + 4).
    __shared__ bool isLast;
    __syncthreads();                 // CTA-order all global stores
    if (t == 0) {
        __threadfence();             // cumulative release for the block
        bool last = false;
        const int k = b & (NGRP - 1);
        const unsigned expect = (k < (NBLK & (NGRP - 1))) ? (NBLK / NGRP + 1)
                                                          : (NBLK / NGRP);
        unsigned r = atomicAdd(&g_grp[k].v, 1u);
        if (r == expect - 1) {       // this group is complete
            unsigned r2 = atomicAdd(&g_super.v, 1u);
            last = (r2 == NGRP - 1);
        }
        isLast = last;
    }
    __syncthreads();
    if (!isLast) return;
    if (t == 0) __threadfence();     // cumulative acquire
    __syncthreads();

    // ---- Phase 2: finalize (last block only) ----
    // Colsum partials: thread (sl, cg) folds blocks sl, sl+32, ... (4-5 each).
    const int cg = t & 31;
    const int sl = t >> 5;           // 0..31
    {
        float4 ax = z, ay = z;
        for (int bb = sl; bb < NBLK; bb += 32) {
            ax = f4add(ax, g_csx4[bb * 32 + cg]);
            ay = f4add(ay, g_csy4[bb * 32 + cg]);
        }
        shx[sl * 32 + cg] = ax;
        shy[sl * 32 + cg] = ay;
    }
    __syncthreads();

    __shared__ double sP;
    __shared__ double sc[3];
    if (t < 32) {
        // Full colsums for column group t, then P partial in double.
        float4 ax = shx[t], ay = shy[t];
        #pragma unroll
        for (int k = 1; k < 32; k++) {
            ax = f4add(ax, shx[k * 32 + t]);
            ay = f4add(ay, shy[k * 32 + t]);
        }
        double p = (double)ax.x * (double)ay.x + (double)ax.y * (double)ay.y
                 + (double)ax.z * (double)ay.z + (double)ax.w * (double)ay.w;
        #pragma unroll
        for (int o = 16; o; o >>= 1)
            p += __shfl_down_sync(0xffffffffu, p, o);
        if (lane == 0) sP = p;
    } else if (t < 128) {
        // Warps 1..3: reduce the three 148-entry scalar arrays (fixed order).
        const int w = s - 1;         // 0..2
        const float* src = (w == 0) ? g_ssx : (w == 1) ? g_ssy : g_dxy;
        double acc = 0.0;
        for (int i = lane; i < NBLK; i += 32)
            acc += (double)src[i];
        #pragma unroll
        for (int o = 16; o; o >>= 1)
            acc += __shfl_down_sync(0xffffffffu, acc, o);
        if (lane == 0) sc[w] = acc;
    }
    __syncthreads();

    if (t == 0) {
        double Nn   = (double)N;
        double loss = (Nn - 1.0) * (sc[0] + sc[1]) - 2.0 * sP + 2.0 * sc[2];
        out[0] = (float)(loss / (2.0 * Nn * (Nn - 1.0)));
    }
    // Reset counters for the next graph replay (parallel, all done here).
    if (t >= 128 && t < 128 + NGRP) g_grp[t - 128].v = 0;
    if (t == 200) g_super.v = 0;
}

extern "C" void kernel_launch(void* const* d_in, const int* in_sizes, int n_in,
                              void* d_out, int out_size)
{
    const float4* f1 = (const float4*)d_in[0];
    const float4* f2 = (const float4*)d_in[1];
    // d_in[2] = label (int64) — mathematically unused by the reference.

    const int N      = in_sizes[0] / DCOLS;   // 8192
    const int total4 = in_sizes[0] / 4;       // float4 count per tensor

    cl_fused_kernel<<<NBLK, NTHR>>>(f1, f2, total4, N, (float*)d_out);
}

// round 15
// speedup vs baseline: 1.1963x; 1.1963x over previous
#include <cuda_runtime.h>
#include <cuda_bf16.h>

// ContrastiveLoss via closed-form separable reduction, ONE fused kernel.
// loss = [(N-1)(Sx+Sy) - 2*dot(colsum_x, colsum_y) + 2*sum_i x_i.y_i] / (2N(N-1))
// Label is unused.
//
// Converged best configuration (R7): 64 blocks x 1024 threads; each thread
// does exactly 4 float4 loads per tensor (8 back-to-back LDG.128, L2-only
// via __ldcg). Two-level last-block election (8 padded group counters).
// Fixed-order reductions -> deterministic across graph replays.

#define NBLK 64
#define NTHR 1024
#define NTOT (NBLK * NTHR)      // 65536 threads
#define DCOLS 128
#define NGRP 8                  // election groups
#define GRP_SZ (NBLK / NGRP)    // 8 blocks per group

__device__ float4 g_csx4[NBLK * 32];   // per-block column sums (128 cols)
__device__ float4 g_csy4[NBLK * 32];
__device__ float  g_ssx[NBLK];
__device__ float  g_ssy[NBLK];
__device__ float  g_dxy[NBLK];

struct __align__(128) PadCtr { unsigned int v; unsigned int pad[31]; };
__device__ PadCtr g_grp[NGRP];         // zero-init; last block resets
__device__ PadCtr g_super;

__device__ __forceinline__ float dot4(float4 a, float4 b) {
    return fmaf(a.x, b.x, fmaf(a.y, b.y, fmaf(a.z, b.z, a.w * b.w)));
}
__device__ __forceinline__ float4 f4add(float4 a, float4 b) {
    return make_float4(a.x + b.x, a.y + b.y, a.z + b.z, a.w + b.w);
}

__global__ void __launch_bounds__(NTHR, 1)
cl_fused_kernel(const float4* __restrict__ f1,
                const float4* __restrict__ f2,
                int total4,          // N * 32 float4 per tensor
                int N,
                float* __restrict__ out)
{
    const int t = threadIdx.x;
    const int b = blockIdx.x;
    const int g = b * NTHR + t;
    const int s = t >> 5;            // warp id 0..31
    const int lane = t & 31;

    // ---- Phase 1: exactly 4 float4 per tensor, all 8 loads front-batched ----
    float4 z = make_float4(0.f, 0.f, 0.f, 0.f);
    float4 x0 = z, x1 = z, x2 = z, x3 = z;
    float4 y0 = z, y1 = z, y2 = z, y3 = z;
    if (total4 == 4 * NTOT) {        // exact fit (N=8192, D=128): no predicates
        x0 = __ldcg(&f1[g]);            y0 = __ldcg(&f2[g]);
        x1 = __ldcg(&f1[g + NTOT]);     y1 = __ldcg(&f2[g + NTOT]);
        x2 = __ldcg(&f1[g + 2 * NTOT]); y2 = __ldcg(&f2[g + 2 * NTOT]);
        x3 = __ldcg(&f1[g + 3 * NTOT]); y3 = __ldcg(&f2[g + 3 * NTOT]);
    } else {
        if (g            < total4) { x0 = f1[g];            y0 = f2[g]; }
        if (g + NTOT     < total4) { x1 = f1[g + NTOT];     y1 = f2[g + NTOT]; }
        if (g + 2 * NTOT < total4) { x2 = f1[g + 2 * NTOT]; y2 = f2[g + 2 * NTOT]; }
        if (g + 3 * NTOT < total4) { x3 = f1[g + 3 * NTOT]; y3 = f2[g + 3 * NTOT]; }
    }

    float4 cx4 = f4add(f4add(x0, x1), f4add(x2, x3));
    float4 cy4 = f4add(f4add(y0, y1), f4add(y2, y3));
    float ssx = (dot4(x0, x0) + dot4(x1, x1)) + (dot4(x2, x2) + dot4(x3, x3));
    float ssy = (dot4(y0, y0) + dot4(y1, y1)) + (dot4(y2, y2) + dot4(y3, y3));
    float dxy = (dot4(x0, y0) + dot4(x1, y1)) + (dot4(x2, y2) + dot4(x3, y3));

    // ---- Block reduce colsums: sum float4 across the 32 warps per lane ----
    __shared__ float4 shx[NTHR];     // 16 KB, reused by finalize
    __shared__ float4 shy[NTHR];     // 16 KB
    shx[t] = cx4;
    shy[t] = cy4;
    __syncthreads();
    if (t < 32) {
        float4 ax = shx[t], ay = shy[t];
        #pragma unroll
        for (int w = 1; w < 32; w++) {
            ax = f4add(ax, shx[w * 32 + t]);
            ay = f4add(ay, shy[w * 32 + t]);
        }
        g_csx4[b * 32 + t] = ax;     // coalesced 512B store
        g_csy4[b * 32 + t] = ay;
    }

    // ---- Block reduce the 3 scalars (shuffle tree, fixed order) ----
    {
        float a = ssx, e = ssy, d = dxy;
        #pragma unroll
        for (int o = 16; o; o >>= 1) {
            a += __shfl_down_sync(0xffffffffu, a, o);
            e += __shfl_down_sync(0xffffffffu, e, o);
            d += __shfl_down_sync(0xffffffffu, d, o);
        }
        __shared__ float w0[32], w1[32], w2[32];
        if (lane == 0) { w0[s] = a; w1[s] = e; w2[s] = d; }
        __syncthreads();
        if (s == 0) {
            float a2 = w0[lane], e2 = w1[lane], d2 = w2[lane];
            #pragma unroll
            for (int o = 16; o; o >>= 1) {
                a2 += __shfl_down_sync(0xffffffffu, a2, o);
                e2 += __shfl_down_sync(0xffffffffu, e2, o);
                d2 += __shfl_down_sync(0xffffffffu, d2, o);
            }
            if (lane == 0) { g_ssx[b] = a2; g_ssy[b] = e2; g_dxy[b] = d2; }
        }
    }

    // ---- Two-level last-block election (short serialized atomic chains) ----
    __shared__ bool isLast;
    __syncthreads();                 // CTA-order all global stores
    if (t == 0) {
        __threadfence();             // cumulative release for the block
        bool last = false;
        unsigned r = atomicAdd(&g_grp[b & (NGRP - 1)].v, 1u);
        if (r == GRP_SZ - 1) {       // this group is complete
            unsigned r2 = atomicAdd(&g_super.v, 1u);
            last = (r2 == NGRP - 1);
        }
        isLast = last;
    }
    __syncthreads();
    if (!isLast) return;
    if (t == 0) __threadfence();     // cumulative acquire
    __syncthreads();

    // ---- Phase 2: finalize (last block only) ----
    // Colsum partials: thread (sl, cg) folds 2 blocks with float4 loads.
    const int cg = t & 31;
    const int sl = t >> 5;           // 0..31, each covers blocks 2sl, 2sl+1
    float4 px = f4add(g_csx4[(2 * sl) * 32 + cg], g_csx4[(2 * sl + 1) * 32 + cg]);
    float4 py = f4add(g_csy4[(2 * sl) * 32 + cg], g_csy4[(2 * sl + 1) * 32 + cg]);
    shx[sl * 32 + cg] = px;
    shy[sl * 32 + cg] = py;
    __syncthreads();

    __shared__ double sP;
    __shared__ double sc[3];
    if (t < 32) {
        // Full colsums for column group t, then P partial in double.
        float4 ax = shx[t], ay = shy[t];
        #pragma unroll
        for (int k = 1; k < 32; k++) {
            ax = f4add(ax, shx[k * 32 + t]);
            ay = f4add(ay, shy[k * 32 + t]);
        }
        double p = (double)ax.x * (double)ay.x + (double)ax.y * (double)ay.y
                 + (double)ax.z * (double)ay.z + (double)ax.w * (double)ay.w;
        #pragma unroll
        for (int o = 16; o; o >>= 1)
            p += __shfl_down_sync(0xffffffffu, p, o);
        if (lane == 0) sP = p;
    } else if (t < 128) {
        // Warps 1..3: reduce the three 64-entry scalar arrays (fixed order).
        const int w = s - 1;         // 0..2
        const float* src = (w == 0) ? g_ssx : (w == 1) ? g_ssy : g_dxy;
        double acc = (double)src[lane] + (double)src[lane + 32];
        #pragma unroll
        for (int o = 16; o; o >>= 1)
            acc += __shfl_down_sync(0xffffffffu, acc, o);
        if (lane == 0) sc[w] = acc;
    }
    __syncthreads();

    if (t == 0) {
        double Nn   = (double)N;
        double loss = (Nn - 1.0) * (sc[0] + sc[1]) - 2.0 * sP + 2.0 * sc[2];
        out[0] = (float)(loss / (2.0 * Nn * (Nn - 1.0)));
        // Reset counters for the next graph replay (all blocks are done).
        #pragma unroll
        for (int k = 0; k < NGRP; k++) g_grp[k].v = 0;
        g_super.v = 0;
    }
}

extern "C" void kernel_launch(void* const* d_in, const int* in_sizes, int n_in,
                              void* d_out, int out_size)
{
    const float4* f1 = (const float4*)d_in[0];
    const float4* f2 = (const float4*)d_in[1];
    // d_in[2] = label (int64) — mathematically unused by the reference.

    const int N      = in_sizes[0] / DCOLS;   // 8192
    const int total4 = in_sizes[0] / 4;       // float4 count per tensor

    cl_fused_kernel<<<NBLK, NTHR>>>(f1, f2, total4, N, (float*)d_out);
}